// round 15
// baseline (speedup 1.0000x reference)
#include <cuda_runtime.h>
#include <cuda_fp16.h>
#include <stdint.h>

#define NN    65536
#define BG    32
#define NPG   2048
#define ECNT  1048576
#define FIN   128
#define DLAT  32
#define TOT   97
#define KPHI  30
#define SLOT  64
#define XPAD  132                        // X smem row stride in floats (de-banked)
#define GROWS 128                        // gemm tile rows
#define GSM   (16384 + GROWS * XPAD * 4) // 16KB W + 67.6KB X = 84KB -> 1 CTA/SM

typedef unsigned long long ULL;

// ---------------- device scratch ----------------
__device__ int     g_cnt[NN];
__device__ int     g_colb[NN * SLOT + 16];   // byte offsets: src*64, guard-padded to 16
__device__ __half2 g_zha[NN * 16 + 16];      // +guard row (zeros)
__device__ __half2 g_zhb[NN * 16 + 16];
__device__ __half2 g_c0 [NN * 16];           // cats in fp16 (64B rows)
__device__ __half2 g_c1 [NN * 16];
__device__ __half2 g_c2 [NN * 16];
__device__ float   g_z1 [NN + 16];           // +guard (zeros)
__device__ float   g_gsum[BG * 32];

// ---------------- f32x2 helpers ----------------
__device__ __forceinline__ ULL pk2(float x, float y) {
    ULL r; asm("mov.b64 %0,{%1,%2};" : "=l"(r) : "f"(x), "f"(y)); return r;
}
__device__ __forceinline__ void upk2(ULL v, float& x, float& y) {
    asm("mov.b64 {%0,%1},%2;" : "=f"(x), "=f"(y) : "l"(v));
}
__device__ __forceinline__ ULL ffma2(ULL a, ULL b, ULL c) {
    ULL d; asm("fma.rn.f32x2 %0,%1,%2,%3;" : "=l"(d) : "l"(a), "l"(b), "l"(c)); return d;
}
__device__ __forceinline__ float fast_tanh(float x) {
    float e;
    asm("ex2.approx.f32 %0, %1;" : "=f"(e) : "f"(x * 2.8853900817779268f));
    float r;
    asm("rcp.approx.f32 %0, %1;" : "=f"(r) : "f"(e + 1.0f));
    return 1.0f - 2.0f * r;
}
__device__ __forceinline__ float fast_rcp(float x) {
    float r;
    asm("rcp.approx.f32 %0, %1;" : "=f"(r) : "f"(x));
    return r;
}
__device__ __forceinline__ float f4get(float4 v, int q) {
    return (q == 0) ? v.x : (q == 1) ? v.y : (q == 2) ? v.z : v.w;
}

// ---------------- init ----------------
__global__ void zero_kernel() {
    int t = blockIdx.x * blockDim.x + threadIdx.x;
    if (t < NN) g_cnt[t] = 0;
    if (t < BG * 32) g_gsum[t] = 0.0f;
    if (t < 16) {
        g_zha[NN * 16 + t] = __float2half2_rn(0.f);
        g_zhb[NN * 16 + t] = __float2half2_rn(0.f);
        g_z1[NN + t] = 0.0f;
    }
}

// ---------------- adjacency fill: byte offsets ----------------
__global__ void fill_adj_kernel(const int* __restrict__ ei) {
    int e = blockIdx.x * blockDim.x + threadIdx.x;
    if (e >= ECNT) return;
    int s = ei[e];
    int d = ei[ECNT + e];
    int pos = atomicAdd(&g_cnt[d], 1);
    g_colb[d * SLOT + pos] = s * 64;
}

// ---------------- pad adjacency rows to multiple of 16 with guard -----------
__global__ void pad_adj_kernel() {
    int n = blockIdx.x * blockDim.x + threadIdx.x;
    if (n >= NN) return;
    int cnt = g_cnt[n];
    int end = (cnt + 15) & ~15;
    for (int j = cnt; j < end; j++) g_colb[n * SLOT + j] = NN * 64;
}

// ---------------- GEMM: Z[N,32](fp16) = X[N,128] @ W0[128,32] ----------------
// 512 threads, 128 rows/block; X staged to smem (8 indep float4/thread), then
// thread = 2 rows x 4 cols register-blocked compute from smem. 84KB -> 1 CTA,
// but 16 warps/SM (vs 8 in the 256-thread variant).
__global__ void gemm128_kernel(const float* __restrict__ X, const float* __restrict__ W,
                               __half2* __restrict__ Z) {
    extern __shared__ float sm[];
    float* Ws = sm;                 // [128*32]
    float* Xs = sm + FIN * 32;      // [128][XPAD]

    int tid  = threadIdx.x;
    int base = blockIdx.x * GROWS;

    // W copy (1024 float4, 2/thread)
    {
        const float4* Wg = (const float4*)W;
        float4* Wd = (float4*)Ws;
        Wd[tid]       = Wg[tid];
        Wd[tid + 512] = Wg[tid + 512];
    }
    // X tile copy: 4096 float4, 8/thread, fully independent
    {
        const float4* Xg = (const float4*)(X + (size_t)base * FIN);
#pragma unroll
        for (int i = 0; i < 8; i++) {
            int idx = tid + i * 512;
            float4 v = Xg[idx];
            int row = idx >> 5, seg = idx & 31;
            *(float4*)&Xs[row * XPAD + seg * 4] = v;
        }
    }
    __syncthreads();

    int rowp = tid >> 3;            // 0..63 -> row pair
    int colg = (tid & 7) * 4;
    int row0 = base + rowp * 2;
    const float* x0 = &Xs[(rowp * 2 + 0) * XPAD];
    const float* x1 = &Xs[(rowp * 2 + 1) * XPAD];

    ULL a00 = 0, a01 = 0, a10 = 0, a11 = 0;

#pragma unroll 8
    for (int k4 = 0; k4 < FIN; k4 += 4) {
        float4 xa = *(const float4*)&x0[k4];
        float4 xb = *(const float4*)&x1[k4];
#pragma unroll
        for (int q = 0; q < 4; q++) {
            float4 w = *(const float4*)&Ws[(k4 + q) * 32 + colg];
            ULL w01 = pk2(w.x, w.y), w23 = pk2(w.z, w.w);
            float v0 = f4get(xa, q), v1 = f4get(xb, q);
            ULL p0 = pk2(v0, v0), p1 = pk2(v1, v1);
            a00 = ffma2(p0, w01, a00); a01 = ffma2(p0, w23, a01);
            a10 = ffma2(p1, w01, a10); a11 = ffma2(p1, w23, a11);
        }
    }

    {
        float o0, o1, o2, o3;
        upk2(a00, o0, o1); upk2(a01, o2, o3);
        __half2 q0 = __floats2half2_rn(o0, o1);
        __half2 q1 = __floats2half2_rn(o2, o3);
        uint2 st; st.x = *(unsigned*)&q0; st.y = *(unsigned*)&q1;
        *(uint2*)((char*)Z + (size_t)row0 * 64 + colg * 2) = st;
    }
    {
        float o0, o1, o2, o3;
        upk2(a10, o0, o1); upk2(a11, o2, o3);
        __half2 q0 = __floats2half2_rn(o0, o1);
        __half2 q1 = __floats2half2_rn(o2, o3);
        uint2 st; st.x = *(unsigned*)&q0; st.y = *(unsigned*)&q1;
        *(uint2*)((char*)Z + (size_t)(row0 + 1) * 64 + colg * 2) = st;
    }
}

// ---------------- stage adjacency rows for 32 nodes into smem ----------------
__device__ __forceinline__ void stage_idx(int* idxs, int nb, int tid) {
    const int4* src = (const int4*)&g_colb[nb * SLOT];
    int4* dst = (int4*)idxs;
#pragma unroll
    for (int i = tid; i < 512; i += 256) dst[i] = src[i];
}

// ---------------- gather: 8 lanes/node, NO predication (guard-padded) -------
__device__ __forceinline__ void gather4(const __half2* __restrict__ zh,
                                        const int* __restrict__ idxrow,
                                        int node, int deg, int l,
                                        __half2& A0, __half2& A1) {
    const char* zb   = (const char*)zh;
    unsigned    loff = (unsigned)(l * 8);
    uint2 sv = *(const uint2*)(zb + (unsigned)(node * 64) + loff);
    __half2 zz = __float2half2_rn(0.f);
    __half2 p0[4], p1[4];
    p0[0] = *(__half2*)&sv.x; p1[0] = *(__half2*)&sv.y;
    p0[1] = zz; p0[2] = zz; p0[3] = zz;
    p1[1] = zz; p1[2] = zz; p1[3] = zz;

    for (int jb = 0; jb < deg; jb += 16) {
        int4 c0 = *(const int4*)(idxrow + jb);
        int4 c1 = *(const int4*)(idxrow + jb + 4);
        int4 c2 = *(const int4*)(idxrow + jb + 8);
        int4 c3 = *(const int4*)(idxrow + jb + 12);
        uint2 u[16];
        u[0]  = *(const uint2*)(zb + (unsigned)c0.x + loff);
        u[1]  = *(const uint2*)(zb + (unsigned)c0.y + loff);
        u[2]  = *(const uint2*)(zb + (unsigned)c0.z + loff);
        u[3]  = *(const uint2*)(zb + (unsigned)c0.w + loff);
        u[4]  = *(const uint2*)(zb + (unsigned)c1.x + loff);
        u[5]  = *(const uint2*)(zb + (unsigned)c1.y + loff);
        u[6]  = *(const uint2*)(zb + (unsigned)c1.z + loff);
        u[7]  = *(const uint2*)(zb + (unsigned)c1.w + loff);
        u[8]  = *(const uint2*)(zb + (unsigned)c2.x + loff);
        u[9]  = *(const uint2*)(zb + (unsigned)c2.y + loff);
        u[10] = *(const uint2*)(zb + (unsigned)c2.z + loff);
        u[11] = *(const uint2*)(zb + (unsigned)c2.w + loff);
        u[12] = *(const uint2*)(zb + (unsigned)c3.x + loff);
        u[13] = *(const uint2*)(zb + (unsigned)c3.y + loff);
        u[14] = *(const uint2*)(zb + (unsigned)c3.z + loff);
        u[15] = *(const uint2*)(zb + (unsigned)c3.w + loff);
#pragma unroll
        for (int i = 0; i < 16; i++) {
            p0[i & 3] = __hadd2(p0[i & 3], *(__half2*)&u[i].x);
            p1[i & 3] = __hadd2(p1[i & 3], *(__half2*)&u[i].y);
        }
    }
    A0 = __hadd2(__hadd2(p0[0], p0[1]), __hadd2(p0[2], p0[3]));
    A1 = __hadd2(__hadd2(p1[0], p1[1]), __hadd2(p1[2], p1[3]));
}

// ---------------- agg + tanh (fp16 c out) + fused 32->32 GEMM ----------------
__global__ void agg_gemm32_kernel(const __half2* __restrict__ zh, const float* __restrict__ b,
                                  const float* __restrict__ Wn, const float* __restrict__ degs,
                                  __half2* __restrict__ c_out, __half2* __restrict__ z_out) {
    __shared__ float  Wsm[32 * 32];
    __shared__ float  bsm[32];
    __shared__ float2 hs[32][33];
    __shared__ int    idxs[32 * 64];
    int tid = threadIdx.x;
    int nb  = blockIdx.x * 32;
    stage_idx(idxs, nb, tid);
    for (int i = tid; i < 1024; i += 256) Wsm[i] = Wn[i];
    if (tid < 32) bsm[tid] = b[tid];
    __syncthreads();

    int lane = tid & 31;
    int l    = lane & 7;
    int g    = lane >> 3;
    int slot = ((tid >> 5) << 2) + g;
    int node = nb + slot;

    float dv  = degs[node];
    int   deg = (int)(dv + 0.5f) - 1;
    __half2 A0, A1;
    gather4(zh, &idxs[slot * 64], node, deg, l, A0, A1);
    float rinv = fast_rcp(dv);
    float2 f0 = __half22float2(A0), f1 = __half22float2(A1);
    float4 bb = *(const float4*)&bsm[4 * l];
    float h0 = fast_tanh((f0.x + bb.x) * rinv);
    float h1 = fast_tanh((f0.y + bb.y) * rinv);
    float h2 = fast_tanh((f1.x + bb.z) * rinv);
    float h3 = fast_tanh((f1.y + bb.w) * rinv);
    {
        __half2 ch0 = __floats2half2_rn(h0, h1);
        __half2 ch1 = __floats2half2_rn(h2, h3);
        uint2 st; st.x = *(unsigned*)&ch0; st.y = *(unsigned*)&ch1;
        *(uint2*)((char*)c_out + (size_t)node * 64 + l * 8) = st;
    }

    hs[slot][4 * l + 0] = make_float2(h0, h0);
    hs[slot][4 * l + 1] = make_float2(h1, h1);
    hs[slot][4 * l + 2] = make_float2(h2, h2);
    hs[slot][4 * l + 3] = make_float2(h3, h3);
    __syncwarp();

    ULL acc01 = 0, acc23 = 0;
#pragma unroll
    for (int k = 0; k < 32; k++) {
        float2 hk = hs[slot][k];
        float4 w4 = *(const float4*)&Wsm[k * 32 + 4 * l];
        ULL h2p = pk2(hk.x, hk.y);
        acc01 = ffma2(h2p, pk2(w4.x, w4.y), acc01);
        acc23 = ffma2(h2p, pk2(w4.z, w4.w), acc23);
    }
    float z0, z1v, z2, z3;
    upk2(acc01, z0, z1v); upk2(acc23, z2, z3);
    __half2 q0 = __floats2half2_rn(z0, z1v);
    __half2 q1 = __floats2half2_rn(z2, z3);
    uint2 st; st.x = *(unsigned*)&q0; st.y = *(unsigned*)&q1;
    *(uint2*)((char*)z_out + (size_t)node * 64 + l * 8) = st;
}

// ---------------- agg + tanh (fp16 c out) + fused 32->1 GEMM ----------------
__global__ void agg_gemm1_kernel(const __half2* __restrict__ zh, const float* __restrict__ b,
                                 const float* __restrict__ W3, const float* __restrict__ degs,
                                 __half2* __restrict__ c_out, float* __restrict__ z1_out) {
    __shared__ float w3s[32];
    __shared__ float bsm[32];
    __shared__ int   idxs[32 * 64];
    int tid = threadIdx.x;
    int nb  = blockIdx.x * 32;
    stage_idx(idxs, nb, tid);
    if (tid < 32) { w3s[tid] = W3[tid]; bsm[tid] = b[tid]; }
    __syncthreads();

    int lane = tid & 31;
    int l    = lane & 7;
    int g    = lane >> 3;
    int slot = ((tid >> 5) << 2) + g;
    int node = nb + slot;

    float dv  = degs[node];
    int   deg = (int)(dv + 0.5f) - 1;
    __half2 A0, A1;
    gather4(zh, &idxs[slot * 64], node, deg, l, A0, A1);
    float rinv = fast_rcp(dv);
    float2 f0 = __half22float2(A0), f1 = __half22float2(A1);
    float4 bb = *(const float4*)&bsm[4 * l];
    float h0 = fast_tanh((f0.x + bb.x) * rinv);
    float h1 = fast_tanh((f0.y + bb.y) * rinv);
    float h2 = fast_tanh((f1.x + bb.z) * rinv);
    float h3 = fast_tanh((f1.y + bb.w) * rinv);
    {
        __half2 ch0 = __floats2half2_rn(h0, h1);
        __half2 ch1 = __floats2half2_rn(h2, h3);
        uint2 st; st.x = *(unsigned*)&ch0; st.y = *(unsigned*)&ch1;
        *(uint2*)((char*)c_out + (size_t)node * 64 + l * 8) = st;
    }

    float4 w4 = *(const float4*)&w3s[4 * l];
    float v = h0 * w4.x + h1 * w4.y + h2 * w4.z + h3 * w4.w;
    v += __shfl_xor_sync(0xffffffffu, v, 1);
    v += __shfl_xor_sync(0xffffffffu, v, 2);
    v += __shfl_xor_sync(0xffffffffu, v, 4);
    if (l == 0) z1_out[node] = v;
}

// ---------------- fused: layer-3 agg + phi + per-graph reduce ----------------
__global__ void agg1_phi_kernel(const float* __restrict__ z1, const float* __restrict__ b3,
                                const float* __restrict__ degs,
                                const __half2* __restrict__ c0, const __half2* __restrict__ c1,
                                const __half2* __restrict__ c2,
                                const float* __restrict__ phiW, const float* __restrict__ phib) {
    __shared__ float Msm[64 * 100];
    __shared__ float Wt[30 * 100];
    __shared__ float c3s[256];
    __shared__ float bs[32];
    __shared__ float red[8 * 32];

    int tid  = threadIdx.x;
    int lane = tid & 31;
    int wrp  = tid >> 5;
    int nblk = blockIdx.x * 256;

    for (int i = tid; i < TOT * KPHI; i += 256) {
        int k = i / KPHI, o = i - k * KPHI;
        Wt[o * 100 + k] = phiW[i];
    }
    if (tid < KPHI) bs[tid] = phib[tid];

    // layer-3 scalar gather, guard-padded (offsets >>4 for float rows)
    {
        int   n   = nblk + tid;
        float dv  = degs[n];
        int   deg = (int)(dv + 0.5f) - 1;
        const char* zb = (const char*)z1;
        const int* col = &g_colb[n * SLOT];
        float p[4] = {z1[n], 0.f, 0.f, 0.f};
        for (int jb = 0; jb < deg; jb += 16) {
            int4 c0v = *(const int4*)(col + jb);
            int4 c1v = *(const int4*)(col + jb + 4);
            int4 c2v = *(const int4*)(col + jb + 8);
            int4 c3v = *(const int4*)(col + jb + 12);
            float v[16];
            v[0]  = *(const float*)(zb + ((unsigned)c0v.x >> 4));
            v[1]  = *(const float*)(zb + ((unsigned)c0v.y >> 4));
            v[2]  = *(const float*)(zb + ((unsigned)c0v.z >> 4));
            v[3]  = *(const float*)(zb + ((unsigned)c0v.w >> 4));
            v[4]  = *(const float*)(zb + ((unsigned)c1v.x >> 4));
            v[5]  = *(const float*)(zb + ((unsigned)c1v.y >> 4));
            v[6]  = *(const float*)(zb + ((unsigned)c1v.z >> 4));
            v[7]  = *(const float*)(zb + ((unsigned)c1v.w >> 4));
            v[8]  = *(const float*)(zb + ((unsigned)c2v.x >> 4));
            v[9]  = *(const float*)(zb + ((unsigned)c2v.y >> 4));
            v[10] = *(const float*)(zb + ((unsigned)c2v.z >> 4));
            v[11] = *(const float*)(zb + ((unsigned)c2v.w >> 4));
            v[12] = *(const float*)(zb + ((unsigned)c3v.x >> 4));
            v[13] = *(const float*)(zb + ((unsigned)c3v.y >> 4));
            v[14] = *(const float*)(zb + ((unsigned)c3v.z >> 4));
            v[15] = *(const float*)(zb + ((unsigned)c3v.w >> 4));
#pragma unroll
            for (int i = 0; i < 16; i++) p[i & 3] += v[i];
        }
        c3s[tid] = fast_tanh(((p[0] + p[1]) + (p[2] + p[3]) + b3[0]) * fast_rcp(dv));
    }

    float psum = 0.f;

    for (int it = 0; it < 4; it++) {
        int nb = nblk + it * 64;
        __syncthreads();
        for (int i = tid; i < 64 * 16; i += 256) {
            int r = i >> 4, k = i & 15;
            float2 f0 = __half22float2(c0[(size_t)(nb + r) * 16 + k]);
            float2 f1 = __half22float2(c1[(size_t)(nb + r) * 16 + k]);
            float2 f2 = __half22float2(c2[(size_t)(nb + r) * 16 + k]);
            Msm[r * 100 + 2 * k]          = f0.x;
            Msm[r * 100 + 2 * k + 1]      = f0.y;
            Msm[r * 100 + 32 + 2 * k]     = f1.x;
            Msm[r * 100 + 32 + 2 * k + 1] = f1.y;
            Msm[r * 100 + 64 + 2 * k]     = f2.x;
            Msm[r * 100 + 64 + 2 * k + 1] = f2.y;
        }
        if (tid < 64) Msm[tid * 100 + 96] = c3s[it * 64 + tid];
        __syncthreads();

        const float* Mr = &Msm[(wrp * 8) * 100];
        if (lane < KPHI) {
            ULL a0=0,a1=0,a2=0,a3=0,a4=0,a5=0,a6=0,a7=0;
            const float* wrow = &Wt[lane * 100];
#pragma unroll 4
            for (int kk = 0; kk < 96; kk += 4) {
                float4 w = *(const float4*)&wrow[kk];
                ULL w01 = pk2(w.x, w.y), w23 = pk2(w.z, w.w);
                float4 m0 = *(const float4*)&Mr[0 * 100 + kk];
                float4 m1 = *(const float4*)&Mr[1 * 100 + kk];
                float4 m2 = *(const float4*)&Mr[2 * 100 + kk];
                float4 m3 = *(const float4*)&Mr[3 * 100 + kk];
                float4 m4 = *(const float4*)&Mr[4 * 100 + kk];
                float4 m5 = *(const float4*)&Mr[5 * 100 + kk];
                float4 m6 = *(const float4*)&Mr[6 * 100 + kk];
                float4 m7 = *(const float4*)&Mr[7 * 100 + kk];
                a0 = ffma2(pk2(m0.x,m0.y), w01, a0); a0 = ffma2(pk2(m0.z,m0.w), w23, a0);
                a1 = ffma2(pk2(m1.x,m1.y), w01, a1); a1 = ffma2(pk2(m1.z,m1.w), w23, a1);
                a2 = ffma2(pk2(m2.x,m2.y), w01, a2); a2 = ffma2(pk2(m2.z,m2.w), w23, a2);
                a3 = ffma2(pk2(m3.x,m3.y), w01, a3); a3 = ffma2(pk2(m3.z,m3.w), w23, a3);
                a4 = ffma2(pk2(m4.x,m4.y), w01, a4); a4 = ffma2(pk2(m4.z,m4.w), w23, a4);
                a5 = ffma2(pk2(m5.x,m5.y), w01, a5); a5 = ffma2(pk2(m5.z,m5.w), w23, a5);
                a6 = ffma2(pk2(m6.x,m6.y), w01, a6); a6 = ffma2(pk2(m6.z,m6.w), w23, a6);
                a7 = ffma2(pk2(m7.x,m7.y), w01, a7); a7 = ffma2(pk2(m7.z,m7.w), w23, a7);
            }
            float w96 = wrow[96];
            float bb  = bs[lane];
            float sx, sy, s;
            upk2(a0,sx,sy); s = sx+sy + Mr[0*100+96]*w96 + bb; psum += fmaxf(s,0.f);
            upk2(a1,sx,sy); s = sx+sy + Mr[1*100+96]*w96 + bb; psum += fmaxf(s,0.f);
            upk2(a2,sx,sy); s = sx+sy + Mr[2*100+96]*w96 + bb; psum += fmaxf(s,0.f);
            upk2(a3,sx,sy); s = sx+sy + Mr[3*100+96]*w96 + bb; psum += fmaxf(s,0.f);
            upk2(a4,sx,sy); s = sx+sy + Mr[4*100+96]*w96 + bb; psum += fmaxf(s,0.f);
            upk2(a5,sx,sy); s = sx+sy + Mr[5*100+96]*w96 + bb; psum += fmaxf(s,0.f);
            upk2(a6,sx,sy); s = sx+sy + Mr[6*100+96]*w96 + bb; psum += fmaxf(s,0.f);
            upk2(a7,sx,sy); s = sx+sy + Mr[7*100+96]*w96 + bb; psum += fmaxf(s,0.f);
        }
    }

    __syncthreads();
    red[wrp * 32 + lane] = psum;
    __syncthreads();
    if (tid < KPHI) {
        float s = 0.f;
#pragma unroll
        for (int q = 0; q < 8; q++) s += red[q * 32 + tid];
        atomicAdd(&g_gsum[(blockIdx.x >> 3) * 32 + tid], s);
    }
}

// ---------------- rho ----------------
__global__ void rho_kernel(const float* __restrict__ rhoW, const float* __restrict__ rhob,
                           float* __restrict__ out) {
    int t = threadIdx.x;
    int g = t >> 5, o = t & 31;
    float acc = rhob[o];
#pragma unroll
    for (int k = 0; k < KPHI; k++) acc += g_gsum[g * 32 + k] * rhoW[k * 32 + o];
    out[t] = acc;
}

// ---------------- launch ----------------
extern "C" void kernel_launch(void* const* d_in, const int* in_sizes, int n_in,
                              void* d_out, int out_size) {
    const float *node_feat, *node_degs;
    const int*   edge_index;
    const float *W0, *b0, *W1, *b1, *W2, *b2, *W3, *b3, *phiW, *phib, *rhoW, *rhob;

    if (in_sizes[2] == 2 * ECNT) {
        node_feat  = (const float*)d_in[0];
        node_degs  = (const float*)d_in[1];
        edge_index = (const int*)  d_in[2];
        W0 = (const float*)d_in[3];  b0 = (const float*)d_in[4];
        W1 = (const float*)d_in[5];  b1 = (const float*)d_in[6];
        W2 = (const float*)d_in[7];  b2 = (const float*)d_in[8];
        W3 = (const float*)d_in[9];  b3 = (const float*)d_in[10];
        phiW = (const float*)d_in[11]; phib = (const float*)d_in[12];
        rhoW = (const float*)d_in[13]; rhob = (const float*)d_in[14];
    } else {
        node_feat  = (const float*)d_in[0];
        node_degs  = (const float*)d_in[1];
        W0 = (const float*)d_in[2];  b0 = (const float*)d_in[3];
        W1 = (const float*)d_in[4];  b1 = (const float*)d_in[5];
        W2 = (const float*)d_in[6];  b2 = (const float*)d_in[7];
        W3 = (const float*)d_in[8];  b3 = (const float*)d_in[9];
        phiW = (const float*)d_in[10]; phib = (const float*)d_in[11];
        rhoW = (const float*)d_in[12]; rhob = (const float*)d_in[13];
        edge_index = (const int*)d_in[14];
    }

    cudaFuncSetAttribute(gemm128_kernel,
                         cudaFuncAttributeMaxDynamicSharedMemorySize, GSM);

    __half2 *za, *zbuf, *c0b, *c1b, *c2b;
    float *z1b;
    cudaGetSymbolAddress((void**)&za,   g_zha);
    cudaGetSymbolAddress((void**)&zbuf, g_zhb);
    cudaGetSymbolAddress((void**)&c0b,  g_c0);
    cudaGetSymbolAddress((void**)&c1b,  g_c1);
    cudaGetSymbolAddress((void**)&c2b,  g_c2);
    cudaGetSymbolAddress((void**)&z1b,  g_z1);

    zero_kernel<<<NN / 256, 256>>>();
    fill_adj_kernel<<<ECNT / 512, 512>>>(edge_index);
    pad_adj_kernel<<<NN / 256, 256>>>();

    gemm128_kernel<<<NN / GROWS, 512, GSM>>>(node_feat, W0, za);
    agg_gemm32_kernel<<<NN / 32, 256>>>(za, b0, W1, node_degs, c0b, zbuf);
    agg_gemm32_kernel<<<NN / 32, 256>>>(zbuf, b1, W2, node_degs, c1b, za);
    agg_gemm1_kernel<<<NN / 32, 256>>>(za, b2, W3, node_degs, c2b, z1b);
    agg1_phi_kernel<<<NN / 256, 256>>>(z1b, b3, node_degs, c0b, c1b, c2b, phiW, phib);
    rho_kernel<<<1, 1024>>>(rhoW, rhob, (float*)d_out);
}

// round 16
// speedup vs baseline: 1.1131x; 1.1131x over previous
#include <cuda_runtime.h>
#include <cuda_fp16.h>
#include <stdint.h>

#define NN    65536
#define BG    32
#define NPG   2048
#define ECNT  1048576
#define FIN   128
#define DLAT  32
#define TOT   97
#define KPHI  30
#define SLOT  64
#define XPAD  132                        // X smem row stride in floats (de-banked)
#define GROWS 128                        // gemm tile rows
#define GBLK  (NN / GROWS)               // 512 gemm blocks
#define FBLK  512                        // fill blocks (2048 edges each)
#define GSM   (16384 + GROWS * XPAD * 4) // 16KB W + 67.6KB X = 84KB

typedef unsigned long long ULL;

// ---------------- device scratch ----------------
__device__ int     g_cnt[NN];                // kept zero by pad_adj invariant
__device__ int     g_colb[NN * SLOT + 16];   // byte offsets: src*64, guard-padded to 16
__device__ __half2 g_zha[NN * 16 + 16];      // +guard row (zeros)
__device__ __half2 g_zhb[NN * 16 + 16];
__device__ __half2 g_c0 [NN * 16];           // cats in fp16 (64B rows)
__device__ __half2 g_c1 [NN * 16];
__device__ __half2 g_c2 [NN * 16];
__device__ float   g_z1 [NN + 16];           // +guard (zeros)
__device__ float   g_gsum[BG * 32];

// ---------------- f32x2 helpers ----------------
__device__ __forceinline__ ULL pk2(float x, float y) {
    ULL r; asm("mov.b64 %0,{%1,%2};" : "=l"(r) : "f"(x), "f"(y)); return r;
}
__device__ __forceinline__ void upk2(ULL v, float& x, float& y) {
    asm("mov.b64 {%0,%1},%2;" : "=f"(x), "=f"(y) : "l"(v));
}
__device__ __forceinline__ ULL ffma2(ULL a, ULL b, ULL c) {
    ULL d; asm("fma.rn.f32x2 %0,%1,%2,%3;" : "=l"(d) : "l"(a), "l"(b), "l"(c)); return d;
}
__device__ __forceinline__ float fast_tanh(float x) {
    float e;
    asm("ex2.approx.f32 %0, %1;" : "=f"(e) : "f"(x * 2.8853900817779268f));
    float r;
    asm("rcp.approx.f32 %0, %1;" : "=f"(r) : "f"(e + 1.0f));
    return 1.0f - 2.0f * r;
}
__device__ __forceinline__ float fast_rcp(float x) {
    float r;
    asm("rcp.approx.f32 %0, %1;" : "=f"(r) : "f"(x));
    return r;
}
__device__ __forceinline__ float f4get(float4 v, int q) {
    return (q == 0) ? v.x : (q == 1) ? v.y : (q == 2) ? v.z : v.w;
}

// ---------------- FUSED: gemm128 tiles (blocks < GBLK) + adjacency fill ------
// gemm path: 256 threads, 128 rows/block; X staged to smem (16 indep float4/th),
// thread = 4 rows x 4 cols register-blocked from smem (R13 config, 22.8us).
// fill path: blocks [GBLK, GBLK+FBLK) fill adjacency (2048 edges/block) —
// independent work that hides in gemm's DRAM-stall slack.
__global__ void gemm_fill_kernel(const float* __restrict__ X, const float* __restrict__ W,
                                 __half2* __restrict__ Z, const int* __restrict__ ei) {
    extern __shared__ float sm[];
    int tid = threadIdx.x;

    if (blockIdx.x >= GBLK) {
        // ---- fill path ----
        int eb = (blockIdx.x - GBLK) * 2048;
#pragma unroll
        for (int i = 0; i < 8; i++) {
            int e = eb + i * 256 + tid;
            int s = ei[e];
            int d = ei[ECNT + e];
            int pos = atomicAdd(&g_cnt[d], 1);
            g_colb[d * SLOT + pos] = s * 64;
        }
        return;
    }

    // ---- gemm path ----
    float* Ws = sm;                 // [128*32]
    float* Xs = sm + FIN * 32;      // [128][XPAD]
    int base = blockIdx.x * GROWS;

    {
        const float4* Wg = (const float4*)W;
        float4* Wd = (float4*)Ws;
#pragma unroll
        for (int i = 0; i < 4; i++) Wd[tid + i * 256] = Wg[tid + i * 256];
    }
    {
        const float4* Xg = (const float4*)(X + (size_t)base * FIN);
#pragma unroll
        for (int i = 0; i < 16; i++) {
            int idx = tid + i * 256;
            float4 v = Xg[idx];
            int row = idx >> 5, seg = idx & 31;
            *(float4*)&Xs[row * XPAD + seg * 4] = v;
        }
    }
    __syncthreads();

    int rowq = tid >> 3;            // 0..31
    int colg = (tid & 7) * 4;
    int row0 = base + rowq * 4;
    const float* x0 = &Xs[(rowq * 4 + 0) * XPAD];
    const float* x1 = &Xs[(rowq * 4 + 1) * XPAD];
    const float* x2 = &Xs[(rowq * 4 + 2) * XPAD];
    const float* x3 = &Xs[(rowq * 4 + 3) * XPAD];

    ULL a00 = 0, a01 = 0, a10 = 0, a11 = 0;
    ULL a20 = 0, a21 = 0, a30 = 0, a31 = 0;

#pragma unroll 8
    for (int k4 = 0; k4 < FIN; k4 += 4) {
        float4 xa = *(const float4*)&x0[k4];
        float4 xb = *(const float4*)&x1[k4];
        float4 xc = *(const float4*)&x2[k4];
        float4 xd = *(const float4*)&x3[k4];
#pragma unroll
        for (int q = 0; q < 4; q++) {
            float4 w = *(const float4*)&Ws[(k4 + q) * 32 + colg];
            ULL w01 = pk2(w.x, w.y), w23 = pk2(w.z, w.w);
            float v0 = f4get(xa, q), v1 = f4get(xb, q);
            float v2 = f4get(xc, q), v3 = f4get(xd, q);
            ULL p0 = pk2(v0, v0), p1 = pk2(v1, v1);
            ULL p2 = pk2(v2, v2), p3 = pk2(v3, v3);
            a00 = ffma2(p0, w01, a00); a01 = ffma2(p0, w23, a01);
            a10 = ffma2(p1, w01, a10); a11 = ffma2(p1, w23, a11);
            a20 = ffma2(p2, w01, a20); a21 = ffma2(p2, w23, a21);
            a30 = ffma2(p3, w01, a31 * 0 + a30); a31 = ffma2(p3, w23, a31);
        }
    }

    ULL accs[4][2] = {{a00, a01}, {a10, a11}, {a20, a21}, {a30, a31}};
#pragma unroll
    for (int r = 0; r < 4; r++) {
        float o0, o1, o2, o3;
        upk2(accs[r][0], o0, o1);
        upk2(accs[r][1], o2, o3);
        __half2 q0 = __floats2half2_rn(o0, o1);
        __half2 q1 = __floats2half2_rn(o2, o3);
        uint2 st; st.x = *(unsigned*)&q0; st.y = *(unsigned*)&q1;
        *(uint2*)((char*)Z + (size_t)(row0 + r) * 64 + colg * 2) = st;
    }
}

// ---------------- pad adjacency + reset cnt + zero gsum/guards ---------------
__global__ void pad_adj_kernel() {
    int n = blockIdx.x * blockDim.x + threadIdx.x;
    if (n < BG * 32) g_gsum[n] = 0.0f;
    if (n < 16) {
        g_zha[NN * 16 + n] = __float2half2_rn(0.f);
        g_zhb[NN * 16 + n] = __float2half2_rn(0.f);
        g_z1[NN + n] = 0.0f;
    }
    if (n >= NN) return;
    int cnt = g_cnt[n];
    int end = (cnt + 15) & ~15;
    for (int j = cnt; j < end; j++) g_colb[n * SLOT + j] = NN * 64;
    g_cnt[n] = 0;   // restore invariant for next launch/replay
}

// ---------------- stage adjacency rows for 32 nodes into smem ----------------
__device__ __forceinline__ void stage_idx(int* idxs, int nb, int tid) {
    const int4* src = (const int4*)&g_colb[nb * SLOT];
    int4* dst = (int4*)idxs;
#pragma unroll
    for (int i = tid; i < 512; i += 256) dst[i] = src[i];
}

// ---------------- gather: 8 lanes/node, NO predication (guard-padded) -------
__device__ __forceinline__ void gather4(const __half2* __restrict__ zh,
                                        const int* __restrict__ idxrow,
                                        int node, int deg, int l,
                                        __half2& A0, __half2& A1) {
    const char* zb   = (const char*)zh;
    unsigned    loff = (unsigned)(l * 8);
    uint2 sv = *(const uint2*)(zb + (unsigned)(node * 64) + loff);
    __half2 zz = __float2half2_rn(0.f);
    __half2 p0[4], p1[4];
    p0[0] = *(__half2*)&sv.x; p1[0] = *(__half2*)&sv.y;
    p0[1] = zz; p0[2] = zz; p0[3] = zz;
    p1[1] = zz; p1[2] = zz; p1[3] = zz;

    for (int jb = 0; jb < deg; jb += 16) {
        int4 c0 = *(const int4*)(idxrow + jb);
        int4 c1 = *(const int4*)(idxrow + jb + 4);
        int4 c2 = *(const int4*)(idxrow + jb + 8);
        int4 c3 = *(const int4*)(idxrow + jb + 12);
        uint2 u[16];
        u[0]  = *(const uint2*)(zb + (unsigned)c0.x + loff);
        u[1]  = *(const uint2*)(zb + (unsigned)c0.y + loff);
        u[2]  = *(const uint2*)(zb + (unsigned)c0.z + loff);
        u[3]  = *(const uint2*)(zb + (unsigned)c0.w + loff);
        u[4]  = *(const uint2*)(zb + (unsigned)c1.x + loff);
        u[5]  = *(const uint2*)(zb + (unsigned)c1.y + loff);
        u[6]  = *(const uint2*)(zb + (unsigned)c1.z + loff);
        u[7]  = *(const uint2*)(zb + (unsigned)c1.w + loff);
        u[8]  = *(const uint2*)(zb + (unsigned)c2.x + loff);
        u[9]  = *(const uint2*)(zb + (unsigned)c2.y + loff);
        u[10] = *(const uint2*)(zb + (unsigned)c2.z + loff);
        u[11] = *(const uint2*)(zb + (unsigned)c2.w + loff);
        u[12] = *(const uint2*)(zb + (unsigned)c3.x + loff);
        u[13] = *(const uint2*)(zb + (unsigned)c3.y + loff);
        u[14] = *(const uint2*)(zb + (unsigned)c3.z + loff);
        u[15] = *(const uint2*)(zb + (unsigned)c3.w + loff);
#pragma unroll
        for (int i = 0; i < 16; i++) {
            p0[i & 3] = __hadd2(p0[i & 3], *(__half2*)&u[i].x);
            p1[i & 3] = __hadd2(p1[i & 3], *(__half2*)&u[i].y);
        }
    }
    A0 = __hadd2(__hadd2(p0[0], p0[1]), __hadd2(p0[2], p0[3]));
    A1 = __hadd2(__hadd2(p1[0], p1[1]), __hadd2(p1[2], p1[3]));
}

// ---------------- agg + tanh (fp16 c out) + fused 32->32 GEMM ----------------
__global__ void agg_gemm32_kernel(const __half2* __restrict__ zh, const float* __restrict__ b,
                                  const float* __restrict__ Wn, const float* __restrict__ degs,
                                  __half2* __restrict__ c_out, __half2* __restrict__ z_out) {
    __shared__ float  Wsm[32 * 32];
    __shared__ float  bsm[32];
    __shared__ float2 hs[32][33];
    __shared__ int    idxs[32 * 64];
    int tid = threadIdx.x;
    int nb  = blockIdx.x * 32;
    stage_idx(idxs, nb, tid);
    for (int i = tid; i < 1024; i += 256) Wsm[i] = Wn[i];
    if (tid < 32) bsm[tid] = b[tid];
    __syncthreads();

    int lane = tid & 31;
    int l    = lane & 7;
    int g    = lane >> 3;
    int slot = ((tid >> 5) << 2) + g;
    int node = nb + slot;

    float dv  = degs[node];
    int   deg = (int)(dv + 0.5f) - 1;
    __half2 A0, A1;
    gather4(zh, &idxs[slot * 64], node, deg, l, A0, A1);
    float rinv = fast_rcp(dv);
    float2 f0 = __half22float2(A0), f1 = __half22float2(A1);
    float4 bb = *(const float4*)&bsm[4 * l];
    float h0 = fast_tanh((f0.x + bb.x) * rinv);
    float h1 = fast_tanh((f0.y + bb.y) * rinv);
    float h2 = fast_tanh((f1.x + bb.z) * rinv);
    float h3 = fast_tanh((f1.y + bb.w) * rinv);
    {
        __half2 ch0 = __floats2half2_rn(h0, h1);
        __half2 ch1 = __floats2half2_rn(h2, h3);
        uint2 st; st.x = *(unsigned*)&ch0; st.y = *(unsigned*)&ch1;
        *(uint2*)((char*)c_out + (size_t)node * 64 + l * 8) = st;
    }

    hs[slot][4 * l + 0] = make_float2(h0, h0);
    hs[slot][4 * l + 1] = make_float2(h1, h1);
    hs[slot][4 * l + 2] = make_float2(h2, h2);
    hs[slot][4 * l + 3] = make_float2(h3, h3);
    __syncwarp();

    ULL acc01 = 0, acc23 = 0;
#pragma unroll
    for (int k = 0; k < 32; k++) {
        float2 hk = hs[slot][k];
        float4 w4 = *(const float4*)&Wsm[k * 32 + 4 * l];
        ULL h2p = pk2(hk.x, hk.y);
        acc01 = ffma2(h2p, pk2(w4.x, w4.y), acc01);
        acc23 = ffma2(h2p, pk2(w4.z, w4.w), acc23);
    }
    float z0, z1v, z2, z3;
    upk2(acc01, z0, z1v); upk2(acc23, z2, z3);
    __half2 q0 = __floats2half2_rn(z0, z1v);
    __half2 q1 = __floats2half2_rn(z2, z3);
    uint2 st; st.x = *(unsigned*)&q0; st.y = *(unsigned*)&q1;
    *(uint2*)((char*)z_out + (size_t)node * 64 + l * 8) = st;
}

// ---------------- agg + tanh (fp16 c out) + fused 32->1 GEMM ----------------
__global__ void agg_gemm1_kernel(const __half2* __restrict__ zh, const float* __restrict__ b,
                                 const float* __restrict__ W3, const float* __restrict__ degs,
                                 __half2* __restrict__ c_out, float* __restrict__ z1_out) {
    __shared__ float w3s[32];
    __shared__ float bsm[32];
    __shared__ int   idxs[32 * 64];
    int tid = threadIdx.x;
    int nb  = blockIdx.x * 32;
    stage_idx(idxs, nb, tid);
    if (tid < 32) { w3s[tid] = W3[tid]; bsm[tid] = b[tid]; }
    __syncthreads();

    int lane = tid & 31;
    int l    = lane & 7;
    int g    = lane >> 3;
    int slot = ((tid >> 5) << 2) + g;
    int node = nb + slot;

    float dv  = degs[node];
    int   deg = (int)(dv + 0.5f) - 1;
    __half2 A0, A1;
    gather4(zh, &idxs[slot * 64], node, deg, l, A0, A1);
    float rinv = fast_rcp(dv);
    float2 f0 = __half22float2(A0), f1 = __half22float2(A1);
    float4 bb = *(const float4*)&bsm[4 * l];
    float h0 = fast_tanh((f0.x + bb.x) * rinv);
    float h1 = fast_tanh((f0.y + bb.y) * rinv);
    float h2 = fast_tanh((f1.x + bb.z) * rinv);
    float h3 = fast_tanh((f1.y + bb.w) * rinv);
    {
        __half2 ch0 = __floats2half2_rn(h0, h1);
        __half2 ch1 = __floats2half2_rn(h2, h3);
        uint2 st; st.x = *(unsigned*)&ch0; st.y = *(unsigned*)&ch1;
        *(uint2*)((char*)c_out + (size_t)node * 64 + l * 8) = st;
    }

    float4 w4 = *(const float4*)&w3s[4 * l];
    float v = h0 * w4.x + h1 * w4.y + h2 * w4.z + h3 * w4.w;
    v += __shfl_xor_sync(0xffffffffu, v, 1);
    v += __shfl_xor_sync(0xffffffffu, v, 2);
    v += __shfl_xor_sync(0xffffffffu, v, 4);
    if (l == 0) z1_out[node] = v;
}

// ---------------- fused: layer-3 agg + phi + per-graph reduce ----------------
__global__ void agg1_phi_kernel(const float* __restrict__ z1, const float* __restrict__ b3,
                                const float* __restrict__ degs,
                                const __half2* __restrict__ c0, const __half2* __restrict__ c1,
                                const __half2* __restrict__ c2,
                                const float* __restrict__ phiW, const float* __restrict__ phib) {
    __shared__ float Msm[64 * 100];
    __shared__ float Wt[30 * 100];
    __shared__ float c3s[256];
    __shared__ float bs[32];
    __shared__ float red[8 * 32];

    int tid  = threadIdx.x;
    int lane = tid & 31;
    int wrp  = tid >> 5;
    int nblk = blockIdx.x * 256;

    for (int i = tid; i < TOT * KPHI; i += 256) {
        int k = i / KPHI, o = i - k * KPHI;
        Wt[o * 100 + k] = phiW[i];
    }
    if (tid < KPHI) bs[tid] = phib[tid];

    {
        int   n   = nblk + tid;
        float dv  = degs[n];
        int   deg = (int)(dv + 0.5f) - 1;
        const char* zb = (const char*)z1;
        const int* col = &g_colb[n * SLOT];
        float p[4] = {z1[n], 0.f, 0.f, 0.f};
        for (int jb = 0; jb < deg; jb += 16) {
            int4 c0v = *(const int4*)(col + jb);
            int4 c1v = *(const int4*)(col + jb + 4);
            int4 c2v = *(const int4*)(col + jb + 8);
            int4 c3v = *(const int4*)(col + jb + 12);
            float v[16];
            v[0]  = *(const float*)(zb + ((unsigned)c0v.x >> 4));
            v[1]  = *(const float*)(zb + ((unsigned)c0v.y >> 4));
            v[2]  = *(const float*)(zb + ((unsigned)c0v.z >> 4));
            v[3]  = *(const float*)(zb + ((unsigned)c0v.w >> 4));
            v[4]  = *(const float*)(zb + ((unsigned)c1v.x >> 4));
            v[5]  = *(const float*)(zb + ((unsigned)c1v.y >> 4));
            v[6]  = *(const float*)(zb + ((unsigned)c1v.z >> 4));
            v[7]  = *(const float*)(zb + ((unsigned)c1v.w >> 4));
            v[8]  = *(const float*)(zb + ((unsigned)c2v.x >> 4));
            v[9]  = *(const float*)(zb + ((unsigned)c2v.y >> 4));
            v[10] = *(const float*)(zb + ((unsigned)c2v.z >> 4));
            v[11] = *(const float*)(zb + ((unsigned)c2v.w >> 4));
            v[12] = *(const float*)(zb + ((unsigned)c3v.x >> 4));
            v[13] = *(const float*)(zb + ((unsigned)c3v.y >> 4));
            v[14] = *(const float*)(zb + ((unsigned)c3v.z >> 4));
            v[15] = *(const float*)(zb + ((unsigned)c3v.w >> 4));
#pragma unroll
            for (int i = 0; i < 16; i++) p[i & 3] += v[i];
        }
        c3s[tid] = fast_tanh(((p[0] + p[1]) + (p[2] + p[3]) + b3[0]) * fast_rcp(dv));
    }

    float psum = 0.f;

    for (int it = 0; it < 4; it++) {
        int nb = nblk + it * 64;
        __syncthreads();
        for (int i = tid; i < 64 * 16; i += 256) {
            int r = i >> 4, k = i & 15;
            float2 f0 = __half22float2(c0[(size_t)(nb + r) * 16 + k]);
            float2 f1 = __half22float2(c1[(size_t)(nb + r) * 16 + k]);
            float2 f2 = __half22float2(c2[(size_t)(nb + r) * 16 + k]);
            Msm[r * 100 + 2 * k]          = f0.x;
            Msm[r * 100 + 2 * k + 1]      = f0.y;
            Msm[r * 100 + 32 + 2 * k]     = f1.x;
            Msm[r * 100 + 32 + 2 * k + 1] = f1.y;
            Msm[r * 100 + 64 + 2 * k]     = f2.x;
            Msm[r * 100 + 64 + 2 * k + 1] = f2.y;
        }
        if (tid < 64) Msm[tid * 100 + 96] = c3s[it * 64 + tid];
        __syncthreads();

        const float* Mr = &Msm[(wrp * 8) * 100];
        if (lane < KPHI) {
            ULL a0=0,a1=0,a2=0,a3=0,a4=0,a5=0,a6=0,a7=0;
            const float* wrow = &Wt[lane * 100];
#pragma unroll 4
            for (int kk = 0; kk < 96; kk += 4) {
                float4 w = *(const float4*)&wrow[kk];
                ULL w01 = pk2(w.x, w.y), w23 = pk2(w.z, w.w);
                float4 m0 = *(const float4*)&Mr[0 * 100 + kk];
                float4 m1 = *(const float4*)&Mr[1 * 100 + kk];
                float4 m2 = *(const float4*)&Mr[2 * 100 + kk];
                float4 m3 = *(const float4*)&Mr[3 * 100 + kk];
                float4 m4 = *(const float4*)&Mr[4 * 100 + kk];
                float4 m5 = *(const float4*)&Mr[5 * 100 + kk];
                float4 m6 = *(const float4*)&Mr[6 * 100 + kk];
                float4 m7 = *(const float4*)&Mr[7 * 100 + kk];
                a0 = ffma2(pk2(m0.x,m0.y), w01, a0); a0 = ffma2(pk2(m0.z,m0.w), w23, a0);
                a1 = ffma2(pk2(m1.x,m1.y), w01, a1); a1 = ffma2(pk2(m1.z,m1.w), w23, a1);
                a2 = ffma2(pk2(m2.x,m2.y), w01, a2); a2 = ffma2(pk2(m2.z,m2.w), w23, a2);
                a3 = ffma2(pk2(m3.x,m3.y), w01, a3); a3 = ffma2(pk2(m3.z,m3.w), w23, a3);
                a4 = ffma2(pk2(m4.x,m4.y), w01, a4); a4 = ffma2(pk2(m4.z,m4.w), w23, a4);
                a5 = ffma2(pk2(m5.x,m5.y), w01, a5); a5 = ffma2(pk2(m5.z,m5.w), w23, a5);
                a6 = ffma2(pk2(m6.x,m6.y), w01, a6); a6 = ffma2(pk2(m6.z,m6.w), w23, a6);
                a7 = ffma2(pk2(m7.x,m7.y), w01, a7); a7 = ffma2(pk2(m7.z,m7.w), w23, a7);
            }
            float w96 = wrow[96];
            float bb  = bs[lane];
            float sx, sy, s;
            upk2(a0,sx,sy); s = sx+sy + Mr[0*100+96]*w96 + bb; psum += fmaxf(s,0.f);
            upk2(a1,sx,sy); s = sx+sy + Mr[1*100+96]*w96 + bb; psum += fmaxf(s,0.f);
            upk2(a2,sx,sy); s = sx+sy + Mr[2*100+96]*w96 + bb; psum += fmaxf(s,0.f);
            upk2(a3,sx,sy); s = sx+sy + Mr[3*100+96]*w96 + bb; psum += fmaxf(s,0.f);
            upk2(a4,sx,sy); s = sx+sy + Mr[4*100+96]*w96 + bb; psum += fmaxf(s,0.f);
            upk2(a5,sx,sy); s = sx+sy + Mr[5*100+96]*w96 + bb; psum += fmaxf(s,0.f);
            upk2(a6,sx,sy); s = sx+sy + Mr[6*100+96]*w96 + bb; psum += fmaxf(s,0.f);
            upk2(a7,sx,sy); s = sx+sy + Mr[7*100+96]*w96 + bb; psum += fmaxf(s,0.f);
        }
    }

    __syncthreads();
    red[wrp * 32 + lane] = psum;
    __syncthreads();
    if (tid < KPHI) {
        float s = 0.f;
#pragma unroll
        for (int q = 0; q < 8; q++) s += red[q * 32 + tid];
        atomicAdd(&g_gsum[(blockIdx.x >> 3) * 32 + tid], s);
    }
}

// ---------------- rho ----------------
__global__ void rho_kernel(const float* __restrict__ rhoW, const float* __restrict__ rhob,
                           float* __restrict__ out) {
    int t = threadIdx.x;
    int g = t >> 5, o = t & 31;
    float acc = rhob[o];
#pragma unroll
    for (int k = 0; k < KPHI; k++) acc += g_gsum[g * 32 + k] * rhoW[k * 32 + o];
    out[t] = acc;
}

// ---------------- launch ----------------
extern "C" void kernel_launch(void* const* d_in, const int* in_sizes, int n_in,
                              void* d_out, int out_size) {
    const float *node_feat, *node_degs;
    const int*   edge_index;
    const float *W0, *b0, *W1, *b1, *W2, *b2, *W3, *b3, *phiW, *phib, *rhoW, *rhob;

    if (in_sizes[2] == 2 * ECNT) {
        node_feat  = (const float*)d_in[0];
        node_degs  = (const float*)d_in[1];
        edge_index = (const int*)  d_in[2];
        W0 = (const float*)d_in[3];  b0 = (const float*)d_in[4];
        W1 = (const float*)d_in[5];  b1 = (const float*)d_in[6];
        W2 = (const float*)d_in[7];  b2 = (const float*)d_in[8];
        W3 = (const float*)d_in[9];  b3 = (const float*)d_in[10];
        phiW = (const float*)d_in[11]; phib = (const float*)d_in[12];
        rhoW = (const float*)d_in[13]; rhob = (const float*)d_in[14];
    } else {
        node_feat  = (const float*)d_in[0];
        node_degs  = (const float*)d_in[1];
        W0 = (const float*)d_in[2];  b0 = (const float*)d_in[3];
        W1 = (const float*)d_in[4];  b1 = (const float*)d_in[5];
        W2 = (const float*)d_in[6];  b2 = (const float*)d_in[7];
        W3 = (const float*)d_in[8];  b3 = (const float*)d_in[9];
        phiW = (const float*)d_in[10]; phib = (const float*)d_in[11];
        rhoW = (const float*)d_in[12]; rhob = (const float*)d_in[13];
        edge_index = (const int*)d_in[14];
    }

    cudaFuncSetAttribute(gemm_fill_kernel,
                         cudaFuncAttributeMaxDynamicSharedMemorySize, GSM);

    __half2 *za, *zbuf, *c0b, *c1b, *c2b;
    float *z1b;
    cudaGetSymbolAddress((void**)&za,   g_zha);
    cudaGetSymbolAddress((void**)&zbuf, g_zhb);
    cudaGetSymbolAddress((void**)&c0b,  g_c0);
    cudaGetSymbolAddress((void**)&c1b,  g_c1);
    cudaGetSymbolAddress((void**)&c2b,  g_c2);
    cudaGetSymbolAddress((void**)&z1b,  g_z1);

    // fused gemm128 + adjacency fill (independent work, shared launch)
    gemm_fill_kernel<<<GBLK + FBLK, 256, GSM>>>(node_feat, W0, za, edge_index);
    // pad adjacency to 16-multiples with guards; resets g_cnt; zeros gsum/guards
    pad_adj_kernel<<<NN / 256, 256>>>();

    agg_gemm32_kernel<<<NN / 32, 256>>>(za, b0, W1, node_degs, c0b, zbuf);
    agg_gemm32_kernel<<<NN / 32, 256>>>(zbuf, b1, W2, node_degs, c1b, za);
    agg_gemm1_kernel<<<NN / 32, 256>>>(za, b2, W3, node_degs, c2b, z1b);
    agg1_phi_kernel<<<NN / 256, 256>>>(z1b, b3, node_degs, c0b, c1b, c2b, phiW, phib);
    rho_kernel<<<1, 1024>>>(rhoW, rhob, (float*)d_out);
}